// round 15
// baseline (speedup 1.0000x reference)
#include <cuda_runtime.h>
#include <cuda_bf16.h>
#include <math_constants.h>

// Problem constants (fixed by setup_inputs)
#define NPTS  16384
#define BATCH 8
#define M     2048
#define CH    128

#define CAP       3072               // per-batch bucket capacity (mean 2048, sd ~42)
#define CHUNK_PTS 16                 // points per block (8 warps x 2 points)
#define NCHUNKS   (CAP / CHUNK_PTS)  // 192
#define FULL 0xffffffffu

typedef unsigned long long ull;

// Device scratch (no allocs allowed)
__device__ float g_featsT[BATCH * M * CH];   // (B, m, C)
__device__ float g_ksoa[BATCH * 3 * M];      // coords SoA: [b][xyz][m]
__device__ int   g_bucket[BATCH * CAP];      // point ids grouped by batch
__device__ int   g_cnt[BATCH];               // per-batch counts
__device__ ull   g_keys[3 * NPTS];           // per-point top-3 keys (idx field also carries b<<11)

// ---------------------------------------------------------------------------
// f32x2 packed helpers. Per-lane results are bit-identical to the scalar
// FADD/FFMA chain (IEEE rn each half, same association).
// ---------------------------------------------------------------------------
__device__ __forceinline__ ull pack2(float lo, float hi) {
    ull r; asm("mov.b64 %0, {%1, %2};" : "=l"(r) : "f"(lo), "f"(hi)); return r;
}
__device__ __forceinline__ void unpack2(ull v, float& lo, float& hi) {
    asm("mov.b64 {%0, %1}, %2;" : "=f"(lo), "=f"(hi) : "l"(v));   // reg-pair alias, free
}
__device__ __forceinline__ ull add2(ull a, ull b) {
    ull r; asm("add.rn.f32x2 %0, %1, %2;" : "=l"(r) : "l"(a), "l"(b)); return r;
}
__device__ __forceinline__ ull mul2(ull a, ull b) {
    ull r; asm("mul.rn.f32x2 %0, %1, %2;" : "=l"(r) : "l"(a), "l"(b)); return r;
}
__device__ __forceinline__ ull fma2(ull a, ull b, ull c) {
    ull r; asm("fma.rn.f32x2 %0, %1, %2, %3;" : "=l"(r) : "l"(a), "l"(b), "l"(c)); return r;
}

// ---------------------------------------------------------------------------
// Feats transpose (B,C,m)->(B,m,C), TWO 32x32 XOR-swizzled tiles per block.
// Runs on a forked side stream, concurrent with prep/bucket/distance.
// ---------------------------------------------------------------------------
__global__ void __launch_bounds__(256)
transpose_kernel(const float* __restrict__ feats)
{
    const int t = threadIdx.x;
    // element (c,j) of each tile at tile[c*8 + ((j>>2) ^ ((c>>2)&7))].comp(j&3)
    __shared__ float4 tileA[32 * 8];
    __shared__ float4 tileB[32 * 8];
    const int b  = blockIdx.z;
    const int j0 = blockIdx.x * 64;       // m tile (two 32-wide halves)
    const int c0 = blockIdx.y * 32;       // channel tile

    {   // load: thread t -> channel c = t>>3, float4-chunk m4 = t&7
        const int c  = t >> 3;
        const int m4 = t & 7;
        const float* rowp = &feats[((size_t)(b * CH + c0 + c)) * M + j0];
        const float4 vA = *(const float4*)&rowp[m4 * 4];
        const float4 vB = *(const float4*)&rowp[32 + m4 * 4];
        const int sw = c * 8 + (m4 ^ ((c >> 2) & 7));
        tileA[sw] = vA;
        tileB[sw] = vB;
    }
    __syncthreads();
    {   // store: thread t -> m row j = t>>3, channel-chunk q = t&7
        const int j = t >> 3;
        const int q = t & 7;
        const int col4 = j >> 2;
        const int comp = j & 3;
        const float* tfA = (const float*)tileA;
        const float* tfB = (const float*)tileB;
        float vA[4], vB[4];
        #pragma unroll
        for (int i = 0; i < 4; i++) {
            const int c = 4 * q + i;
            const int off = c * 32 + ((col4 ^ ((c >> 2) & 7)) * 4) + comp;
            vA[i] = tfA[off];
            vB[i] = tfB[off];
        }
        *(float4*)&g_featsT[((size_t)(b * M + j0 + j)) * CH + c0 + 4 * q] =
            make_float4(vA[0], vA[1], vA[2], vA[3]);
        *(float4*)&g_featsT[((size_t)(b * M + j0 + 32 + j)) * CH + c0 + 4 * q] =
            make_float4(vB[0], vB[1], vB[2], vB[3]);
    }
}

// ---------------------------------------------------------------------------
// Prep: coord SoA split + counter zero. 64 blocks x 256.
// ---------------------------------------------------------------------------
__global__ void prep_kernel(const float* __restrict__ known)
{
    const int i = blockIdx.x * 256 + threadIdx.x;   // 0..16383
    if (i < BATCH) g_cnt[i] = 0;
    const int b = i >> 11;          // i / M
    const int j = i & (M - 1);
    g_ksoa[(b * 3 + 0) * M + j] = known[3 * i + 0];
    g_ksoa[(b * 3 + 1) * M + j] = known[3 * i + 1];
    g_ksoa[(b * 3 + 2) * M + j] = known[3 * i + 2];
}

// ---------------------------------------------------------------------------
// Bucket points by batch (order nondeterministic; output invariant to it).
// ---------------------------------------------------------------------------
__global__ void bucket_kernel(const int* __restrict__ batch_inds)
{
    __shared__ int hist[BATCH];
    __shared__ int base[BATCH];
    __shared__ int loc[BATCH];
    const int t = threadIdx.x;
    if (t < BATCH) { hist[t] = 0; loc[t] = 0; }
    __syncthreads();

    const int p = blockIdx.x * blockDim.x + t;
    const int b = batch_inds[p];
    atomicAdd(&hist[b], 1);
    __syncthreads();

    if (t < BATCH) base[t] = atomicAdd(&g_cnt[t], hist[t]);
    __syncthreads();

    const int r   = atomicAdd(&loc[b], 1);
    const int pos = base[b] + r;
    if (pos < CAP) g_bucket[b * CAP + pos] = p;
}

// ---------------------------------------------------------------------------
// Warp-collective EXACT top-3 update (REDUX loop, early-breaking).
// Candidate index of lane src is off + 2*src (monotone in src -> lowest
// owner lane = lowest index). Keys (d_bits << 32 | idx): uint order of
// non-negative floats is monotone; ties -> lower index (jax top_k).
// ---------------------------------------------------------------------------
__device__ __forceinline__ void topk_update(bool pass, float d, int off, int lane,
                                            ull& k0, ull& k1, ull& k2)
{
    unsigned cur = pass ? __float_as_uint(d) : 0xFFFFFFFFu;
    while (true) {
        const unsigned mind   = __reduce_min_sync(FULL, cur);
        const unsigned owners = __ballot_sync(FULL, cur == mind);
        const int      src    = __ffs(owners) - 1;      // lowest lane = lowest idx
        const ull      mkey   = ((ull)mind << 32) | (unsigned)(off + (src << 1));
        if (mkey >= k2) break;
        const bool b0 = mkey < k0, b1 = mkey < k1;
        k2 = b1 ? k1 : mkey;
        k1 = b0 ? k0 : (b1 ? mkey : k1);
        k0 = b0 ? mkey : k0;
        if (lane == src) cur = 0xFFFFFFFFu;             // consume winner
        if (!__any_sync(FULL, cur <= (unsigned)(k2 >> 32))) break;  // cheap pre-break
    }
}

// ---------------------------------------------------------------------------
// Distance kernel (R13 structure): block = (chunk of 16 points, batch).
// SoA coords in 24KB smem; each warp 2 points; each lane one candidate PAIR
// per 64-candidate window via 3 LDS.64 + packed f32x2 math (bit-identical
// rounding). One vote per window; REDUX merge on triggering windows.
// Writes top-3 keys (b packed into idx bits 11-13 AFTER all comparisons).
// ---------------------------------------------------------------------------
__global__ void __launch_bounds__(256)
knn_dist_kernel(const float* __restrict__ unknown)
{
    __shared__ __align__(16) float sco[3 * M];    // sx | sy | sz, 24 KB
    const int b     = blockIdx.y;
    const int cnt   = g_cnt[b];
    const int start = blockIdx.x * CHUNK_PTS;
    if (start >= cnt) return;                     // uniform exit, pre-sync

    const int t    = threadIdx.x;
    const int lane = t & 31;
    const int w    = t >> 5;

    // Point loads first so their latency overlaps the smem fill.
    int pidA = -1, pidB = -1;
    ull nxA = 0, nyA = 0, nzA = 0;
    ull nxB = 0, nyB = 0, nzB = 0;
    float t2A = -CUDART_INF_F, t2B = -CUDART_INF_F;   // inactive -> never passes

    const int ibA = start + w * 2;
    const int ibB = ibA + 1;
    if (ibA < cnt) {
        pidA = g_bucket[b * CAP + ibA];
        const float x = unknown[pidA * 3 + 0];
        const float y = unknown[pidA * 3 + 1];
        const float z = unknown[pidA * 3 + 2];
        nxA = pack2(-x, -x); nyA = pack2(-y, -y); nzA = pack2(-z, -z);
        t2A = CUDART_INF_F;
    }
    if (ibB < cnt) {
        pidB = g_bucket[b * CAP + ibB];
        const float x = unknown[pidB * 3 + 0];
        const float y = unknown[pidB * 3 + 1];
        const float z = unknown[pidB * 3 + 2];
        nxB = pack2(-x, -x); nyB = pack2(-y, -y); nzB = pack2(-z, -z);
        t2B = CUDART_INF_F;
    }

    {
        const float4* __restrict__ src4 = (const float4*)(g_ksoa + b * 3 * M);
        #pragma unroll
        for (int i = 0; i < 3 * M / 4 / 256; i++)
            ((float4*)sco)[t + 256 * i] = src4[t + 256 * i];
    }
    __syncthreads();

    const float* sx = sco;
    const float* sy = sco + M;
    const float* sz = sco + 2 * M;

    ull k0A = ~0ull, k1A = ~0ull, k2A = ~0ull;
    ull k0B = ~0ull, k1B = ~0ull, k2B = ~0ull;

    #pragma unroll 4
    for (int it = 0; it < M / 64; it++) {
        const int cb = it * 64 + 2 * lane;        // lane's candidate pair: cb, cb+1
        const ull cx2 = *(const ull*)&sx[cb];
        const ull cy2 = *(const ull*)&sy[cb];
        const ull cz2 = *(const ull*)&sz[cb];

        // packed distances: per-half identical to fmaf(dx,dx,fmaf(dy,dy,dz*dz))
        const ull dxA = add2(cx2, nxA), dyA = add2(cy2, nyA), dzA = add2(cz2, nzA);
        const ull ddA = fma2(dxA, dxA, fma2(dyA, dyA, mul2(dzA, dzA)));
        const ull dxB = add2(cx2, nxB), dyB = add2(cy2, nyB), dzB = add2(cz2, nzB);
        const ull ddB = fma2(dxB, dxB, fma2(dyB, dyB, mul2(dzB, dzB)));

        float dA1, dA2, dB1, dB2;
        unpack2(ddA, dA1, dA2);                   // free (register-pair halves)
        unpack2(ddB, dB1, dB2);

        const bool pA1 = dA1 <= t2A, pA2 = dA2 <= t2A;
        const bool pB1 = dB1 <= t2B, pB2 = dB2 <= t2B;

        if (__any_sync(FULL, (pA1 | pA2) | (pB1 | pB2))) {
            const int base = it * 64;
            if (__any_sync(FULL, pA1 | pA2)) {
                if (__any_sync(FULL, pA1)) topk_update(pA1, dA1, base,     lane, k0A, k1A, k2A);
                if (__any_sync(FULL, pA2)) topk_update(pA2, dA2, base + 1, lane, k0A, k1A, k2A);
                t2A = __uint_as_float((unsigned)(k2A >> 32));
            }
            if (__any_sync(FULL, pB1 | pB2)) {
                if (__any_sync(FULL, pB1)) topk_update(pB1, dB1, base,     lane, k0B, k1B, k2B);
                if (__any_sync(FULL, pB2)) topk_update(pB2, dB2, base + 1, lane, k0B, k1B, k2B);
                t2B = __uint_as_float((unsigned)(k2B >> 32));
            }
        }
    }

    // Store keys (b packed into spare idx bits; idx <= 2047 fits 11 bits).
    const ull btag = (ull)b << 11;
    if (lane == 0 && pidA >= 0) {
        ull* kp = g_keys + 3 * (size_t)pidA;
        kp[0] = k0A | btag; kp[1] = k1A | btag; kp[2] = k2A | btag;
    }
    if (lane == 1 && pidB >= 0) {
        ull* kp = g_keys + 3 * (size_t)pidB;
        kp[0] = k0B | btag; kp[1] = k1B | btag; kp[2] = k2B | btag;
    }
}

// ---------------------------------------------------------------------------
// Gather: one warp per point. Weights from key distances; 3 float4 row
// gathers from g_featsT; combine; store.
// ---------------------------------------------------------------------------
__global__ void __launch_bounds__(256)
gather_kernel(float* __restrict__ out)
{
    const int p    = blockIdx.x * 8 + (threadIdx.x >> 5);
    const int lane = threadIdx.x & 31;

    const ull* kp = g_keys + 3 * (size_t)p;
    const ull k0 = kp[0], k1 = kp[1], k2 = kp[2];   // broadcast loads

    const float d0 = __uint_as_float((unsigned)(k0 >> 32));
    const float d1 = __uint_as_float((unsigned)(k1 >> 32));
    const float d2 = __uint_as_float((unsigned)(k2 >> 32));
    float w0 = 1.0f / (sqrtf(d0) + 1e-8f);
    float w1 = 1.0f / (sqrtf(d1) + 1e-8f);
    float w2 = 1.0f / (sqrtf(d2) + 1e-8f);
    const float inv = 1.0f / (w0 + w1 + w2);
    w0 *= inv; w1 *= inv; w2 *= inv;

    const unsigned lo0 = (unsigned)k0;
    const int b  = (lo0 >> 11) & 7;
    const int i0 = lo0 & (M - 1);
    const int i1 = (unsigned)k1 & (M - 1);
    const int i2 = (unsigned)k2 & (M - 1);

    const float4 a0 = ((const float4*)(g_featsT + ((size_t)(b * M + i0)) * CH))[lane];
    const float4 a1 = ((const float4*)(g_featsT + ((size_t)(b * M + i1)) * CH))[lane];
    const float4 a2 = ((const float4*)(g_featsT + ((size_t)(b * M + i2)) * CH))[lane];
    float4 o;
    o.x = fmaf(w0, a0.x, fmaf(w1, a1.x, w2 * a2.x));
    o.y = fmaf(w0, a0.y, fmaf(w1, a1.y, w2 * a2.y));
    o.z = fmaf(w0, a0.z, fmaf(w1, a1.z, w2 * a2.z));
    o.w = fmaf(w0, a0.w, fmaf(w1, a1.w, w2 * a2.w));
    ((float4*)out)[(size_t)p * (CH / 4) + lane] = o;
}

// ---------------------------------------------------------------------------
// Launch: fork transpose onto a side stream (event fork/join, capture-legal);
// it overlaps prep + bucket + distance. Join before gather.
// ---------------------------------------------------------------------------
extern "C" void kernel_launch(void* const* d_in, const int* in_sizes, int n_in,
                              void* d_out, int out_size)
{
    const float* unknown     = (const float*)d_in[0];
    const float* known       = (const float*)d_in[1];
    const int*   batch_inds  = (const int*)d_in[2];
    const float* known_feats = (const float*)d_in[3];
    float* out = (float*)d_out;

    static cudaStream_t s2 = nullptr;
    static cudaEvent_t evFork = nullptr, evJoin = nullptr;
    if (s2 == nullptr) {
        cudaStreamCreateWithFlags(&s2, cudaStreamNonBlocking);
        cudaEventCreateWithFlags(&evFork, cudaEventDisableTiming);
        cudaEventCreateWithFlags(&evJoin, cudaEventDisableTiming);
    }

    // Fork: side stream branches off the (captured) default stream.
    cudaEventRecord(evFork, 0);
    cudaStreamWaitEvent(s2, evFork, 0);
    transpose_kernel<<<dim3(M / 64, CH / 32, BATCH), 256, 0, s2>>>(known_feats);
    cudaEventRecord(evJoin, s2);

    // Main branch.
    prep_kernel<<<NPTS / 256, 256>>>(known);
    bucket_kernel<<<NPTS / 256, 256>>>(batch_inds);
    knn_dist_kernel<<<dim3(NCHUNKS, BATCH), 256>>>(unknown);

    // Join: gather needs g_featsT.
    cudaStreamWaitEvent(0, evJoin, 0);
    gather_kernel<<<NPTS / 8, 256>>>(out);
}

// round 16
// speedup vs baseline: 1.1533x; 1.1533x over previous
#include <cuda_runtime.h>
#include <cuda_bf16.h>
#include <math_constants.h>

// Problem constants (fixed by setup_inputs)
#define NPTS  16384
#define BATCH 8
#define M     2048
#define CH    128

#define CAP       3072               // per-batch bucket capacity (mean 2048, sd ~42)
#define CHUNK_PTS 16                 // points per block (8 warps x 2 points)
#define NCHUNKS   (CAP / CHUNK_PTS)  // 192
#define FULL 0xffffffffu

#define TR_BLOCKS   1024             // transpose blocks: 32 j-tiles x 4 c-tiles x 8 batches
#define DIST_BLOCKS (NCHUNKS * BATCH)   // 1536

typedef unsigned long long ull;

// Device scratch (no allocs allowed)
__device__ float g_featsT[BATCH * M * CH];   // (B, m, C)
__device__ float g_ksoa[BATCH * 3 * M];      // coords SoA: [b][xyz][m]
__device__ int   g_bucket[BATCH * CAP];      // point ids grouped by batch
__device__ int   g_cnt[BATCH];               // per-batch counts
__device__ int   g_done;                     // transpose-blocks-finished counter

// ---------------------------------------------------------------------------
// f32x2 packed helpers. Per-lane results are bit-identical to the scalar
// FADD/FFMA chain (IEEE rn each half, same association).
// ---------------------------------------------------------------------------
__device__ __forceinline__ ull pack2(float lo, float hi) {
    ull r; asm("mov.b64 %0, {%1, %2};" : "=l"(r) : "f"(lo), "f"(hi)); return r;
}
__device__ __forceinline__ void unpack2(ull v, float& lo, float& hi) {
    asm("mov.b64 {%0, %1}, %2;" : "=f"(lo), "=f"(hi) : "l"(v));   // reg-pair alias, free
}
__device__ __forceinline__ ull add2(ull a, ull b) {
    ull r; asm("add.rn.f32x2 %0, %1, %2;" : "=l"(r) : "l"(a), "l"(b)); return r;
}
__device__ __forceinline__ ull mul2(ull a, ull b) {
    ull r; asm("mul.rn.f32x2 %0, %1, %2;" : "=l"(r) : "l"(a), "l"(b)); return r;
}
__device__ __forceinline__ ull fma2(ull a, ull b, ull c) {
    ull r; asm("fma.rn.f32x2 %0, %1, %2, %3;" : "=l"(r) : "l"(a), "l"(b), "l"(c)); return r;
}

// ---------------------------------------------------------------------------
// Prep: coord SoA split + zero counters. Runs before everything.
// ---------------------------------------------------------------------------
__global__ void prep_kernel(const float* __restrict__ known)
{
    const int i = blockIdx.x * 256 + threadIdx.x;   // 0..16383
    if (i == 0) g_done = 0;
    if (i < BATCH) g_cnt[i] = 0;
    const int b = i >> 11;          // i / M
    const int j = i & (M - 1);
    g_ksoa[(b * 3 + 0) * M + j] = known[3 * i + 0];
    g_ksoa[(b * 3 + 1) * M + j] = known[3 * i + 1];
    g_ksoa[(b * 3 + 2) * M + j] = known[3 * i + 2];
}

// ---------------------------------------------------------------------------
// Bucket points by batch (order nondeterministic; output invariant to it).
// ---------------------------------------------------------------------------
__global__ void bucket_kernel(const int* __restrict__ batch_inds)
{
    __shared__ int hist[BATCH];
    __shared__ int base[BATCH];
    __shared__ int loc[BATCH];
    const int t = threadIdx.x;
    if (t < BATCH) { hist[t] = 0; loc[t] = 0; }
    __syncthreads();

    const int p = blockIdx.x * blockDim.x + t;
    const int b = batch_inds[p];
    atomicAdd(&hist[b], 1);
    __syncthreads();

    if (t < BATCH) base[t] = atomicAdd(&g_cnt[t], hist[t]);
    __syncthreads();

    const int r   = atomicAdd(&loc[b], 1);
    const int pos = base[b] + r;
    if (pos < CAP) g_bucket[b * CAP + pos] = p;
}

// ---------------------------------------------------------------------------
// Warp-collective EXACT top-3 update (REDUX loop, early-breaking).
// Candidate index of lane src is off + 2*src (monotone in src -> lowest
// owner lane = lowest index). Keys (d_bits << 32 | idx): uint order of
// non-negative floats is monotone; ties -> lower index (jax top_k).
// ---------------------------------------------------------------------------
__device__ __forceinline__ void topk_update(bool pass, float d, int off, int lane,
                                            ull& k0, ull& k1, ull& k2)
{
    unsigned cur = pass ? __float_as_uint(d) : 0xFFFFFFFFu;
    while (true) {
        const unsigned mind   = __reduce_min_sync(FULL, cur);
        const unsigned owners = __ballot_sync(FULL, cur == mind);
        const int      src    = __ffs(owners) - 1;      // lowest lane = lowest idx
        const ull      mkey   = ((ull)mind << 32) | (unsigned)(off + (src << 1));
        if (mkey >= k2) break;
        const bool b0 = mkey < k0, b1 = mkey < k1;
        k2 = b1 ? k1 : mkey;
        k1 = b0 ? k0 : (b1 ? mkey : k1);
        k0 = b0 ? mkey : k0;
        if (lane == src) cur = 0xFFFFFFFFu;             // consume winner
        if (!__any_sync(FULL, cur <= (unsigned)(k2 >> 32))) break;  // cheap pre-break
    }
}

// Weights + feature gather + output write for one finished point.
__device__ __forceinline__ void write_point(int pid, int b, ull k0, ull k1, ull k2,
                                            int lane, float* __restrict__ out)
{
    const float d0 = __uint_as_float((unsigned)(k0 >> 32));
    const float d1 = __uint_as_float((unsigned)(k1 >> 32));
    const float d2 = __uint_as_float((unsigned)(k2 >> 32));
    float w0 = 1.0f / (sqrtf(d0) + 1e-8f);
    float w1 = 1.0f / (sqrtf(d1) + 1e-8f);
    float w2 = 1.0f / (sqrtf(d2) + 1e-8f);
    const float inv = 1.0f / (w0 + w1 + w2);
    w0 *= inv; w1 *= inv; w2 *= inv;

    const int i0 = (int)(unsigned)k0;
    const int i1 = (int)(unsigned)k1;
    const int i2 = (int)(unsigned)k2;

    const float4 a0 = ((const float4*)(g_featsT + ((size_t)(b * M + i0)) * CH))[lane];
    const float4 a1 = ((const float4*)(g_featsT + ((size_t)(b * M + i1)) * CH))[lane];
    const float4 a2 = ((const float4*)(g_featsT + ((size_t)(b * M + i2)) * CH))[lane];
    float4 o;
    o.x = fmaf(w0, a0.x, fmaf(w1, a1.x, w2 * a2.x));
    o.y = fmaf(w0, a0.y, fmaf(w1, a1.y, w2 * a2.y));
    o.z = fmaf(w0, a0.z, fmaf(w1, a1.z, w2 * a2.z));
    o.w = fmaf(w0, a0.w, fmaf(w1, a1.w, w2 * a2.w));
    ((float4*)out)[(size_t)pid * (CH / 4) + lane] = o;
}

// ---------------------------------------------------------------------------
// FUSED kernel. bid < TR_BLOCKS: transpose block (launched FIRST -> fills the
// first wave, retires in ~6us, signals g_done). Else: distance block (R13
// body). Distance blocks need g_featsT only at the terminal write_point, by
// which time all transpose blocks have long retired -> the spin is one read.
// Deadlock-free: all transpose bids precede all distance bids, and the first
// wave (~740 slots) is entirely transpose blocks.
// ---------------------------------------------------------------------------
__global__ void __launch_bounds__(256)
fused_main_kernel(const float* __restrict__ unknown,
                  const float* __restrict__ feats,
                  float* __restrict__ out)
{
    __shared__ __align__(16) float sco[3 * M];    // 24 KB (aliased by transpose tiles)
    const int bid = blockIdx.x;
    const int t   = threadIdx.x;

    if (bid < TR_BLOCKS) {
        // ---- transpose block: two 32x32 XOR-swizzled tiles (64-wide m tile)
        float4* tileA = (float4*)sco;             // 4 KB
        float4* tileB = (float4*)(sco + 1024);    // 4 KB
        const int b   = bid >> 7;                 // 128 tiles per batch
        const int rem = bid & 127;
        const int j0  = (rem >> 2) * 64;          // m tile
        const int c0  = (rem & 3) * 32;           // channel tile

        {   // load: thread t -> channel c = t>>3, float4-chunk m4 = t&7
            const int c  = t >> 3;
            const int m4 = t & 7;
            const float* rowp = &feats[((size_t)(b * CH + c0 + c)) * M + j0];
            const float4 vA = *(const float4*)&rowp[m4 * 4];
            const float4 vB = *(const float4*)&rowp[32 + m4 * 4];
            const int sw = c * 8 + (m4 ^ ((c >> 2) & 7));
            tileA[sw] = vA;
            tileB[sw] = vB;
        }
        __syncthreads();
        {   // store: thread t -> m row j = t>>3, channel-chunk q = t&7
            const int j = t >> 3;
            const int q = t & 7;
            const int col4 = j >> 2;
            const int comp = j & 3;
            const float* tfA = (const float*)tileA;
            const float* tfB = (const float*)tileB;
            float vA[4], vB[4];
            #pragma unroll
            for (int i = 0; i < 4; i++) {
                const int c = 4 * q + i;
                const int off = c * 32 + ((col4 ^ ((c >> 2) & 7)) * 4) + comp;
                vA[i] = tfA[off];
                vB[i] = tfB[off];
            }
            *(float4*)&g_featsT[((size_t)(b * M + j0 + j)) * CH + c0 + 4 * q] =
                make_float4(vA[0], vA[1], vA[2], vA[3]);
            *(float4*)&g_featsT[((size_t)(b * M + j0 + 32 + j)) * CH + c0 + 4 * q] =
                make_float4(vB[0], vB[1], vB[2], vB[3]);
        }
        __syncthreads();
        __threadfence();                          // release g_featsT writes
        if (t == 0) atomicAdd(&g_done, 1);
        return;
    }

    // ---- distance block (R13 body) ----
    const int db    = bid - TR_BLOCKS;
    const int b     = db / NCHUNKS;
    const int chunk = db - b * NCHUNKS;
    const int cnt   = g_cnt[b];
    const int start = chunk * CHUNK_PTS;
    if (start >= cnt) return;                     // uniform exit, pre-sync

    const int lane = t & 31;
    const int w    = t >> 5;

    // Point loads first so their latency overlaps the smem fill.
    int pidA = -1, pidB = -1;
    ull nxA = 0, nyA = 0, nzA = 0;
    ull nxB = 0, nyB = 0, nzB = 0;
    float t2A = -CUDART_INF_F, t2B = -CUDART_INF_F;   // inactive -> never passes

    const int ibA = start + w * 2;
    const int ibB = ibA + 1;
    if (ibA < cnt) {
        pidA = g_bucket[b * CAP + ibA];
        const float x = unknown[pidA * 3 + 0];
        const float y = unknown[pidA * 3 + 1];
        const float z = unknown[pidA * 3 + 2];
        nxA = pack2(-x, -x); nyA = pack2(-y, -y); nzA = pack2(-z, -z);
        t2A = CUDART_INF_F;
    }
    if (ibB < cnt) {
        pidB = g_bucket[b * CAP + ibB];
        const float x = unknown[pidB * 3 + 0];
        const float y = unknown[pidB * 3 + 1];
        const float z = unknown[pidB * 3 + 2];
        nxB = pack2(-x, -x); nyB = pack2(-y, -y); nzB = pack2(-z, -z);
        t2B = CUDART_INF_F;
    }

    {
        const float4* __restrict__ src4 = (const float4*)(g_ksoa + b * 3 * M);
        #pragma unroll
        for (int i = 0; i < 3 * M / 4 / 256; i++)
            ((float4*)sco)[t + 256 * i] = src4[t + 256 * i];
    }
    __syncthreads();

    const float* sx = sco;
    const float* sy = sco + M;
    const float* sz = sco + 2 * M;

    ull k0A = ~0ull, k1A = ~0ull, k2A = ~0ull;
    ull k0B = ~0ull, k1B = ~0ull, k2B = ~0ull;

    #pragma unroll 4
    for (int it = 0; it < M / 64; it++) {
        const int cb = it * 64 + 2 * lane;        // lane's candidate pair: cb, cb+1
        const ull cx2 = *(const ull*)&sx[cb];
        const ull cy2 = *(const ull*)&sy[cb];
        const ull cz2 = *(const ull*)&sz[cb];

        // packed distances: per-half identical to fmaf(dx,dx,fmaf(dy,dy,dz*dz))
        const ull dxA = add2(cx2, nxA), dyA = add2(cy2, nyA), dzA = add2(cz2, nzA);
        const ull ddA = fma2(dxA, dxA, fma2(dyA, dyA, mul2(dzA, dzA)));
        const ull dxB = add2(cx2, nxB), dyB = add2(cy2, nyB), dzB = add2(cz2, nzB);
        const ull ddB = fma2(dxB, dxB, fma2(dyB, dyB, mul2(dzB, dzB)));

        float dA1, dA2, dB1, dB2;
        unpack2(ddA, dA1, dA2);                   // free (register-pair halves)
        unpack2(ddB, dB1, dB2);

        const bool pA1 = dA1 <= t2A, pA2 = dA2 <= t2A;
        const bool pB1 = dB1 <= t2B, pB2 = dB2 <= t2B;

        if (__any_sync(FULL, (pA1 | pA2) | (pB1 | pB2))) {
            const int base = it * 64;
            if (__any_sync(FULL, pA1 | pA2)) {
                if (__any_sync(FULL, pA1)) topk_update(pA1, dA1, base,     lane, k0A, k1A, k2A);
                if (__any_sync(FULL, pA2)) topk_update(pA2, dA2, base + 1, lane, k0A, k1A, k2A);
                t2A = __uint_as_float((unsigned)(k2A >> 32));
            }
            if (__any_sync(FULL, pB1 | pB2)) {
                if (__any_sync(FULL, pB1)) topk_update(pB1, dB1, base,     lane, k0B, k1B, k2B);
                if (__any_sync(FULL, pB2)) topk_update(pB2, dB2, base + 1, lane, k0B, k1B, k2B);
                t2B = __uint_as_float((unsigned)(k2B >> 32));
            }
        }
    }

    // Wait for all transpose blocks (long since done; one L2 read typically).
    if (t == 0) {
        while (atomicAdd(&g_done, 0) < TR_BLOCKS) { }
    }
    __syncthreads();
    __threadfence();                              // acquire g_featsT writes

    if (pidA >= 0) write_point(pidA, b, k0A, k1A, k2A, lane, out);
    if (pidB >= 0) write_point(pidB, b, k0B, k1B, k2B, lane, out);
}

// ---------------------------------------------------------------------------
extern "C" void kernel_launch(void* const* d_in, const int* in_sizes, int n_in,
                              void* d_out, int out_size)
{
    const float* unknown     = (const float*)d_in[0];
    const float* known       = (const float*)d_in[1];
    const int*   batch_inds  = (const int*)d_in[2];
    const float* known_feats = (const float*)d_in[3];
    float* out = (float*)d_out;

    prep_kernel<<<NPTS / 256, 256>>>(known);
    bucket_kernel<<<NPTS / 256, 256>>>(batch_inds);
    fused_main_kernel<<<TR_BLOCKS + DIST_BLOCKS, 256>>>(unknown, known_feats, out);
}

// round 17
// speedup vs baseline: 1.1542x; 1.0009x over previous
#include <cuda_runtime.h>
#include <cuda_bf16.h>
#include <math_constants.h>

// Problem constants (fixed by setup_inputs)
#define NPTS  16384
#define BATCH 8
#define M     2048
#define CH    128

#define CAP       3072               // per-batch bucket capacity (mean 2048, sd ~42)
#define CHUNK_PTS 16                 // points per block (8 warps x 2 points)
#define NCHUNKS   (CAP / CHUNK_PTS)  // 192
#define FULL 0xffffffffu

#define TR_BLOCKS   1024             // transpose blocks: 32 j-tiles x 4 c-tiles x 8 batches
#define DIST_BLOCKS (NCHUNKS * BATCH)   // 1536

typedef unsigned long long ull;

// Device scratch (no allocs allowed). All zero-initialized at module load;
// the fused kernel's last distance block restores the zeroed state each
// launch, so graph replays always start clean.
__device__ float g_featsT[BATCH * M * CH];   // (B, m, C)
__device__ float g_ksoa[BATCH * 3 * M];      // coords SoA: [b][xyz][m]
__device__ int   g_bucket[BATCH * CAP];      // point ids grouped by batch
__device__ int   g_cnt[BATCH];               // per-batch counts   (0 at launch entry)
__device__ int   g_done;                     // transpose-done counter (0 at entry)
__device__ int   g_dist_done;                // distance-done counter  (0 at entry)

// ---------------------------------------------------------------------------
// f32x2 packed helpers. Per-lane results are bit-identical to the scalar
// FADD/FFMA chain (IEEE rn each half, same association).
// ---------------------------------------------------------------------------
__device__ __forceinline__ ull pack2(float lo, float hi) {
    ull r; asm("mov.b64 %0, {%1, %2};" : "=l"(r) : "f"(lo), "f"(hi)); return r;
}
__device__ __forceinline__ void unpack2(ull v, float& lo, float& hi) {
    asm("mov.b64 {%0, %1}, %2;" : "=f"(lo), "=f"(hi) : "l"(v));   // reg-pair alias, free
}
__device__ __forceinline__ ull add2(ull a, ull b) {
    ull r; asm("add.rn.f32x2 %0, %1, %2;" : "=l"(r) : "l"(a), "l"(b)); return r;
}
__device__ __forceinline__ ull mul2(ull a, ull b) {
    ull r; asm("mul.rn.f32x2 %0, %1, %2;" : "=l"(r) : "l"(a), "l"(b)); return r;
}
__device__ __forceinline__ ull fma2(ull a, ull b, ull c) {
    ull r; asm("fma.rn.f32x2 %0, %1, %2, %3;" : "=l"(r) : "l"(a), "l"(b), "l"(c)); return r;
}

// ---------------------------------------------------------------------------
// Bucket + prep fused: SoA coord split AND batch bucketing in one 64x256
// launch. g_cnt is zero on entry (module init / end-of-previous-launch
// cleanup). Bucket order nondeterministic; output invariant to it.
// ---------------------------------------------------------------------------
__global__ void bucket_prep_kernel(const int* __restrict__ batch_inds,
                                   const float* __restrict__ known)
{
    __shared__ int hist[BATCH];
    __shared__ int base[BATCH];
    __shared__ int loc[BATCH];
    const int t = threadIdx.x;
    const int p = blockIdx.x * blockDim.x + t;      // 0..16383

    // --- prep part: SoA split (independent of bucketing) ---
    {
        const int b = p >> 11;          // p / M
        const int j = p & (M - 1);
        g_ksoa[(b * 3 + 0) * M + j] = known[3 * p + 0];
        g_ksoa[(b * 3 + 1) * M + j] = known[3 * p + 1];
        g_ksoa[(b * 3 + 2) * M + j] = known[3 * p + 2];
    }

    // --- bucket part ---
    if (t < BATCH) { hist[t] = 0; loc[t] = 0; }
    __syncthreads();

    const int b = batch_inds[p];
    atomicAdd(&hist[b], 1);
    __syncthreads();

    if (t < BATCH) base[t] = atomicAdd(&g_cnt[t], hist[t]);
    __syncthreads();

    const int r   = atomicAdd(&loc[b], 1);
    const int pos = base[b] + r;
    if (pos < CAP) g_bucket[b * CAP + pos] = p;
}

// ---------------------------------------------------------------------------
// Warp-collective EXACT top-3 update (REDUX loop, early-breaking).
// Candidate index of lane src is off + 2*src (monotone in src -> lowest
// owner lane = lowest index). Keys (d_bits << 32 | idx): uint order of
// non-negative floats is monotone; ties -> lower index (jax top_k).
// ---------------------------------------------------------------------------
__device__ __forceinline__ void topk_update(bool pass, float d, int off, int lane,
                                            ull& k0, ull& k1, ull& k2)
{
    unsigned cur = pass ? __float_as_uint(d) : 0xFFFFFFFFu;
    while (true) {
        const unsigned mind   = __reduce_min_sync(FULL, cur);
        const unsigned owners = __ballot_sync(FULL, cur == mind);
        const int      src    = __ffs(owners) - 1;      // lowest lane = lowest idx
        const ull      mkey   = ((ull)mind << 32) | (unsigned)(off + (src << 1));
        if (mkey >= k2) break;
        const bool b0 = mkey < k0, b1 = mkey < k1;
        k2 = b1 ? k1 : mkey;
        k1 = b0 ? k0 : (b1 ? mkey : k1);
        k0 = b0 ? mkey : k0;
        if (lane == src) cur = 0xFFFFFFFFu;             // consume winner
        if (!__any_sync(FULL, cur <= (unsigned)(k2 >> 32))) break;  // cheap pre-break
    }
}

// Weights + feature gather + output write for one finished point.
__device__ __forceinline__ void write_point(int pid, int b, ull k0, ull k1, ull k2,
                                            int lane, float* __restrict__ out)
{
    const float d0 = __uint_as_float((unsigned)(k0 >> 32));
    const float d1 = __uint_as_float((unsigned)(k1 >> 32));
    const float d2 = __uint_as_float((unsigned)(k2 >> 32));
    float w0 = 1.0f / (sqrtf(d0) + 1e-8f);
    float w1 = 1.0f / (sqrtf(d1) + 1e-8f);
    float w2 = 1.0f / (sqrtf(d2) + 1e-8f);
    const float inv = 1.0f / (w0 + w1 + w2);
    w0 *= inv; w1 *= inv; w2 *= inv;

    const int i0 = (int)(unsigned)k0;
    const int i1 = (int)(unsigned)k1;
    const int i2 = (int)(unsigned)k2;

    const float4 a0 = ((const float4*)(g_featsT + ((size_t)(b * M + i0)) * CH))[lane];
    const float4 a1 = ((const float4*)(g_featsT + ((size_t)(b * M + i1)) * CH))[lane];
    const float4 a2 = ((const float4*)(g_featsT + ((size_t)(b * M + i2)) * CH))[lane];
    float4 o;
    o.x = fmaf(w0, a0.x, fmaf(w1, a1.x, w2 * a2.x));
    o.y = fmaf(w0, a0.y, fmaf(w1, a1.y, w2 * a2.y));
    o.z = fmaf(w0, a0.z, fmaf(w1, a1.z, w2 * a2.z));
    o.w = fmaf(w0, a0.w, fmaf(w1, a1.w, w2 * a2.w));
    ((float4*)out)[(size_t)pid * (CH / 4) + lane] = o;
}

// End-of-launch cleanup: the block that brings g_dist_done to DIST_BLOCKS
// restores the zeroed counter state for the next (graph-replayed) launch.
// Safe: the counter only reaches DIST_BLOCKS after every distance block has
// read g_cnt and finished its g_done spin.
__device__ __forceinline__ void dist_block_retire()
{
    __threadfence();
    const int done = atomicAdd(&g_dist_done, 1) + 1;
    if (done == DIST_BLOCKS) {
        #pragma unroll
        for (int i = 0; i < BATCH; i++) g_cnt[i] = 0;
        g_done = 0;
        __threadfence();
        g_dist_done = 0;
    }
}

// ---------------------------------------------------------------------------
// FUSED kernel. bid < TR_BLOCKS: transpose block (launched FIRST -> fills
// wave 1, retires fast, signals g_done). Else: distance block (R13 body).
// Distance blocks need g_featsT only at the terminal write_point, by which
// time all transpose blocks have long retired -> the spin is one read.
// ---------------------------------------------------------------------------
__global__ void __launch_bounds__(256)
fused_main_kernel(const float* __restrict__ unknown,
                  const float* __restrict__ feats,
                  float* __restrict__ out)
{
    __shared__ __align__(16) float sco[3 * M];    // 24 KB (aliased by transpose tiles)
    const int bid = blockIdx.x;
    const int t   = threadIdx.x;

    if (bid < TR_BLOCKS) {
        // ---- transpose block: two 32x32 XOR-swizzled tiles (64-wide m tile)
        float4* tileA = (float4*)sco;             // 4 KB
        float4* tileB = (float4*)(sco + 1024);    // 4 KB
        const int b   = bid >> 7;                 // 128 tiles per batch
        const int rem = bid & 127;
        const int j0  = (rem >> 2) * 64;          // m tile
        const int c0  = (rem & 3) * 32;           // channel tile

        {   // load: thread t -> channel c = t>>3, float4-chunk m4 = t&7
            const int c  = t >> 3;
            const int m4 = t & 7;
            const float* rowp = &feats[((size_t)(b * CH + c0 + c)) * M + j0];
            const float4 vA = *(const float4*)&rowp[m4 * 4];
            const float4 vB = *(const float4*)&rowp[32 + m4 * 4];
            const int sw = c * 8 + (m4 ^ ((c >> 2) & 7));
            tileA[sw] = vA;
            tileB[sw] = vB;
        }
        __syncthreads();
        {   // store: thread t -> m row j = t>>3, channel-chunk q = t&7
            const int j = t >> 3;
            const int q = t & 7;
            const int col4 = j >> 2;
            const int comp = j & 3;
            const float* tfA = (const float*)tileA;
            const float* tfB = (const float*)tileB;
            float vA[4], vB[4];
            #pragma unroll
            for (int i = 0; i < 4; i++) {
                const int c = 4 * q + i;
                const int off = c * 32 + ((col4 ^ ((c >> 2) & 7)) * 4) + comp;
                vA[i] = tfA[off];
                vB[i] = tfB[off];
            }
            *(float4*)&g_featsT[((size_t)(b * M + j0 + j)) * CH + c0 + 4 * q] =
                make_float4(vA[0], vA[1], vA[2], vA[3]);
            *(float4*)&g_featsT[((size_t)(b * M + j0 + 32 + j)) * CH + c0 + 4 * q] =
                make_float4(vB[0], vB[1], vB[2], vB[3]);
        }
        __syncthreads();
        __threadfence();                          // release g_featsT writes
        if (t == 0) atomicAdd(&g_done, 1);
        return;
    }

    // ---- distance block (R13 body) ----
    const int db    = bid - TR_BLOCKS;
    const int b     = db / NCHUNKS;
    const int chunk = db - b * NCHUNKS;
    const int cnt   = g_cnt[b];
    const int start = chunk * CHUNK_PTS;
    if (start >= cnt) {                           // uniform exit, pre-sync
        if (t == 0) dist_block_retire();
        return;
    }

    const int lane = t & 31;
    const int w    = t >> 5;

    // Point loads first so their latency overlaps the smem fill.
    int pidA = -1, pidB = -1;
    ull nxA = 0, nyA = 0, nzA = 0;
    ull nxB = 0, nyB = 0, nzB = 0;
    float t2A = -CUDART_INF_F, t2B = -CUDART_INF_F;   // inactive -> never passes

    const int ibA = start + w * 2;
    const int ibB = ibA + 1;
    if (ibA < cnt) {
        pidA = g_bucket[b * CAP + ibA];
        const float x = unknown[pidA * 3 + 0];
        const float y = unknown[pidA * 3 + 1];
        const float z = unknown[pidA * 3 + 2];
        nxA = pack2(-x, -x); nyA = pack2(-y, -y); nzA = pack2(-z, -z);
        t2A = CUDART_INF_F;
    }
    if (ibB < cnt) {
        pidB = g_bucket[b * CAP + ibB];
        const float x = unknown[pidB * 3 + 0];
        const float y = unknown[pidB * 3 + 1];
        const float z = unknown[pidB * 3 + 2];
        nxB = pack2(-x, -x); nyB = pack2(-y, -y); nzB = pack2(-z, -z);
        t2B = CUDART_INF_F;
    }

    {
        const float4* __restrict__ src4 = (const float4*)(g_ksoa + b * 3 * M);
        #pragma unroll
        for (int i = 0; i < 3 * M / 4 / 256; i++)
            ((float4*)sco)[t + 256 * i] = src4[t + 256 * i];
    }
    __syncthreads();

    const float* sx = sco;
    const float* sy = sco + M;
    const float* sz = sco + 2 * M;

    ull k0A = ~0ull, k1A = ~0ull, k2A = ~0ull;
    ull k0B = ~0ull, k1B = ~0ull, k2B = ~0ull;

    #pragma unroll 4
    for (int it = 0; it < M / 64; it++) {
        const int cb = it * 64 + 2 * lane;        // lane's candidate pair: cb, cb+1
        const ull cx2 = *(const ull*)&sx[cb];
        const ull cy2 = *(const ull*)&sy[cb];
        const ull cz2 = *(const ull*)&sz[cb];

        // packed distances: per-half identical to fmaf(dx,dx,fmaf(dy,dy,dz*dz))
        const ull dxA = add2(cx2, nxA), dyA = add2(cy2, nyA), dzA = add2(cz2, nzA);
        const ull ddA = fma2(dxA, dxA, fma2(dyA, dyA, mul2(dzA, dzA)));
        const ull dxB = add2(cx2, nxB), dyB = add2(cy2, nyB), dzB = add2(cz2, nzB);
        const ull ddB = fma2(dxB, dxB, fma2(dyB, dyB, mul2(dzB, dzB)));

        float dA1, dA2, dB1, dB2;
        unpack2(ddA, dA1, dA2);                   // free (register-pair halves)
        unpack2(ddB, dB1, dB2);

        const bool pA1 = dA1 <= t2A, pA2 = dA2 <= t2A;
        const bool pB1 = dB1 <= t2B, pB2 = dB2 <= t2B;

        if (__any_sync(FULL, (pA1 | pA2) | (pB1 | pB2))) {
            const int base = it * 64;
            if (__any_sync(FULL, pA1 | pA2)) {
                if (__any_sync(FULL, pA1)) topk_update(pA1, dA1, base,     lane, k0A, k1A, k2A);
                if (__any_sync(FULL, pA2)) topk_update(pA2, dA2, base + 1, lane, k0A, k1A, k2A);
                t2A = __uint_as_float((unsigned)(k2A >> 32));
            }
            if (__any_sync(FULL, pB1 | pB2)) {
                if (__any_sync(FULL, pB1)) topk_update(pB1, dB1, base,     lane, k0B, k1B, k2B);
                if (__any_sync(FULL, pB2)) topk_update(pB2, dB2, base + 1, lane, k0B, k1B, k2B);
                t2B = __uint_as_float((unsigned)(k2B >> 32));
            }
        }
    }

    // Wait for all transpose blocks (long since done; one L2 read typically).
    if (t == 0) {
        while (atomicAdd(&g_done, 0) < TR_BLOCKS) { }
    }
    __syncthreads();
    __threadfence();                              // acquire g_featsT writes

    if (pidA >= 0) write_point(pidA, b, k0A, k1A, k2A, lane, out);
    if (pidB >= 0) write_point(pidB, b, k0B, k1B, k2B, lane, out);

    __syncthreads();
    if (t == 0) dist_block_retire();
}

// ---------------------------------------------------------------------------
extern "C" void kernel_launch(void* const* d_in, const int* in_sizes, int n_in,
                              void* d_out, int out_size)
{
    const float* unknown     = (const float*)d_in[0];
    const float* known       = (const float*)d_in[1];
    const int*   batch_inds  = (const int*)d_in[2];
    const float* known_feats = (const float*)d_in[3];
    float* out = (float*)d_out;

    bucket_prep_kernel<<<NPTS / 256, 256>>>(batch_inds, known);
    fused_main_kernel<<<TR_BLOCKS + DIST_BLOCKS, 256>>>(unknown, known_feats, out);
}